// round 2
// baseline (speedup 1.0000x reference)
#include <cuda_runtime.h>

#define NL 25
#define ED 64
#define HD 8
#define NB 1000
#define NS 512
#define CS 5          // CTAs (batch slices) per layer
#define BPC 200       // batches per CTA

// Scratch (static __device__ arrays; allocation-free per harness rules)
__device__ float g_xproj[NS * NB * 24];              // layer-0 input projections (+bias), 49 MB
__device__ float g_hbuf[24 * NS * NB * HD];          // inter-layer h buffers, 393 MB
__device__ unsigned int g_flags[24 * NS * CS];       // pipeline ready flags

__device__ __forceinline__ void fma8(float* acc, float s, float4 a, float4 b) {
    acc[0] = fmaf(s, a.x, acc[0]); acc[1] = fmaf(s, a.y, acc[1]);
    acc[2] = fmaf(s, a.z, acc[2]); acc[3] = fmaf(s, a.w, acc[3]);
    acc[4] = fmaf(s, b.x, acc[4]); acc[5] = fmaf(s, b.y, acc[5]);
    acc[6] = fmaf(s, b.z, acc[6]); acc[7] = fmaf(s, b.w, acc[7]);
}

__device__ __forceinline__ float sigm(float x) {
    return __fdividef(1.0f, 1.0f + __expf(-x));
}
__device__ __forceinline__ float tanh_f(float x) {
    // tanh(x) = 1 - 2/(exp(2x)+1); exact limits at +/-inf
    return 1.0f - __fdividef(2.0f, __expf(2.0f * x) + 1.0f);
}

__global__ void clear_flags() {
    int i = blockIdx.x * blockDim.x + threadIdx.x;
    if (i < 24 * NS * CS) g_flags[i] = 0u;
}

// xproj[t][b][0:8]=x@Wxz0+bz0, [8:16]=x@Wxr0+br0, [16:24]=x@WxH0+bH0
__global__ void __launch_bounds__(256) precompute_xproj(
    const int* __restrict__ x, const float* __restrict__ emb,
    const float* __restrict__ Wxz0, const float* __restrict__ bz0,
    const float* __restrict__ Wxr0, const float* __restrict__ br0,
    const float* __restrict__ WxH0, const float* __restrict__ bH0)
{
    __shared__ float4 sw4[3][ED][2];   // [mat][k][half]: rows of 8 weights
    __shared__ float sb[24];
    float* swf = (float*)sw4;
    const int tid = threadIdx.x;
    for (int i = tid; i < ED * HD; i += blockDim.x) {
        swf[i]            = Wxz0[i];
        swf[ED * HD + i]  = Wxr0[i];
        swf[2 * ED * HD + i] = WxH0[i];
    }
    if (tid < 8) { sb[tid] = bz0[tid]; sb[8 + tid] = br0[tid]; sb[16 + tid] = bH0[tid]; }
    __syncthreads();

    int i = blockIdx.x * blockDim.x + tid;
    if (i >= NB * NS) return;
    const int b = i / NS, t = i % NS;
    const int idx = x[i];
    const float4* e4 = (const float4*)(emb + (long long)idx * ED);

    float acc[24];
    #pragma unroll
    for (int j = 0; j < 24; j++) acc[j] = sb[j];

    #pragma unroll
    for (int k4 = 0; k4 < ED / 4; k4++) {
        float4 ev = e4[k4];
        float es[4] = {ev.x, ev.y, ev.z, ev.w};
        #pragma unroll
        for (int q = 0; q < 4; q++) {
            const int k = k4 * 4 + q;
            const float ek = es[q];
            fma8(acc,      ek, sw4[0][k][0], sw4[0][k][1]);
            fma8(acc + 8,  ek, sw4[1][k][0], sw4[1][k][1]);
            fma8(acc + 16, ek, sw4[2][k][0], sw4[2][k][1]);
        }
    }
    float4* o4 = (float4*)(g_xproj + ((long long)t * NB + b) * 24);
    o4[0] = make_float4(acc[0], acc[1], acc[2], acc[3]);
    o4[1] = make_float4(acc[4], acc[5], acc[6], acc[7]);
    o4[2] = make_float4(acc[8], acc[9], acc[10], acc[11]);
    o4[3] = make_float4(acc[12], acc[13], acc[14], acc[15]);
    o4[4] = make_float4(acc[16], acc[17], acc[18], acc[19]);
    o4[5] = make_float4(acc[20], acc[21], acc[22], acc[23]);
}

// Persistent layer-pipelined GRU. blockIdx = layer*CS + slice.
__global__ void __launch_bounds__(256, 1) gru_pipeline(
    const float* __restrict__ Whz0, const float* __restrict__ Whr0, const float* __restrict__ WrH0,
    const float* __restrict__ Wxz, const float* __restrict__ Whz, const float* __restrict__ bz,
    const float* __restrict__ Wxr, const float* __restrict__ Whr, const float* __restrict__ br,
    const float* __restrict__ WxH, const float* __restrict__ WrH, const float* __restrict__ bH,
    const float* __restrict__ Why, const float* __restrict__ by,
    float* __restrict__ out, int out_size)
{
    __shared__ float4 sw4[6][HD][2];   // slots: 0 Wxz | 1 Whz | 2 Wxr | 3 Whr | 4 WxH | 5 WrH
    __shared__ float sb[24];
    const int tid = threadIdx.x;
    const int layer = blockIdx.x / CS;
    const int c = blockIdx.x % CS;
    float* swf = (float*)sw4;

    if (layer == 0) {
        // layer-0 slots: 0 = Whz0, 1 = Whr0, 2 = WrH0 (x-part + biases are in g_xproj)
        for (int i = tid; i < HD * HD; i += blockDim.x) {
            swf[i]       = Whz0[i];
            swf[64 + i]  = Whr0[i];
            swf[128 + i] = WrH0[i];
        }
    } else {
        const int off = (layer - 1) * HD * HD;
        for (int i = tid; i < HD * HD; i += blockDim.x) {
            swf[i]        = Wxz[off + i];
            swf[64 + i]   = Whz[off + i];
            swf[128 + i]  = Wxr[off + i];
            swf[192 + i]  = Whr[off + i];
            swf[256 + i]  = WxH[off + i];
            swf[320 + i]  = WrH[off + i];
        }
        if (tid < 8) {
            sb[tid]      = bz[(layer - 1) * 8 + tid];
            sb[8 + tid]  = br[(layer - 1) * 8 + tid];
            sb[16 + tid] = bH[(layer - 1) * 8 + tid];
        }
    }
    __syncthreads();

    const bool active = tid < BPC;
    const int b = c * BPC + tid;
    float h[8];
    #pragma unroll
    for (int j = 0; j < 8; j++) h[j] = 0.f;

    const int lprev = (layer > 0) ? (layer - 1) : 0;
    unsigned int* prodflag = g_flags + (layer * NS) * CS + c;   // used iff layer<24
    unsigned int* consflag = g_flags + (lprev * NS) * CS + c;   // used iff layer>0
    const float* inbase = g_hbuf + ((long long)lprev * NS * NB + b) * HD;
    float*      outbase = g_hbuf + ((long long)layer * NS * NB + b) * HD;
    const float* xpbase = g_xproj + (long long)b * 24;
    const float4 (*wrH)[2] = (layer == 0) ? sw4[2] : sw4[5];

    #pragma unroll 1
    for (int t = 0; t < NS; t++) {
        if (layer > 0) {
            if (tid == 0) {
                const unsigned int* fp = consflag + t * CS;
                unsigned int f;
                do {
                    asm volatile("ld.global.acquire.gpu.b32 %0, [%1];"
                                 : "=r"(f) : "l"(fp) : "memory");
                } while (f == 0u);
            }
            __syncthreads();
        }
        if (active) {
            float az[8], ar[8], aH[8], z[8], r[8], rh[8];
            if (layer == 0) {
                const float4* xp = (const float4*)(xpbase + (long long)t * NB * 24);
                float4 v0 = xp[0], v1 = xp[1], v2 = xp[2], v3 = xp[3], v4 = xp[4], v5 = xp[5];
                az[0]=v0.x; az[1]=v0.y; az[2]=v0.z; az[3]=v0.w;
                az[4]=v1.x; az[5]=v1.y; az[6]=v1.z; az[7]=v1.w;
                ar[0]=v2.x; ar[1]=v2.y; ar[2]=v2.z; ar[3]=v2.w;
                ar[4]=v3.x; ar[5]=v3.y; ar[6]=v3.z; ar[7]=v3.w;
                aH[0]=v4.x; aH[1]=v4.y; aH[2]=v4.z; aH[3]=v4.w;
                aH[4]=v5.x; aH[5]=v5.y; aH[6]=v5.z; aH[7]=v5.w;
                #pragma unroll
                for (int k = 0; k < 8; k++) {
                    const float hv = h[k];
                    fma8(az, hv, sw4[0][k][0], sw4[0][k][1]);
                    fma8(ar, hv, sw4[1][k][0], sw4[1][k][1]);
                }
            } else {
                const float4* xi = (const float4*)(inbase + (long long)t * NB * HD);
                float4 x0 = __ldcg(xi), x1 = __ldcg(xi + 1);
                float xk[8] = {x0.x, x0.y, x0.z, x0.w, x1.x, x1.y, x1.z, x1.w};
                #pragma unroll
                for (int j = 0; j < 8; j++) { az[j] = sb[j]; ar[j] = sb[8 + j]; aH[j] = sb[16 + j]; }
                #pragma unroll
                for (int k = 0; k < 8; k++) {
                    const float xv = xk[k], hv = h[k];
                    fma8(az, xv, sw4[0][k][0], sw4[0][k][1]);
                    fma8(az, hv, sw4[1][k][0], sw4[1][k][1]);
                    fma8(ar, xv, sw4[2][k][0], sw4[2][k][1]);
                    fma8(ar, hv, sw4[3][k][0], sw4[3][k][1]);
                    fma8(aH, xv, sw4[4][k][0], sw4[4][k][1]);
                }
            }
            #pragma unroll
            for (int j = 0; j < 8; j++) { z[j] = sigm(az[j]); r[j] = sigm(ar[j]); }
            #pragma unroll
            for (int k = 0; k < 8; k++) rh[k] = h[k] * r[k];
            #pragma unroll
            for (int k = 0; k < 8; k++) fma8(aH, rh[k], wrH[k][0], wrH[k][1]);
            #pragma unroll
            for (int j = 0; j < 8; j++) {
                const float Hc = tanh_f(aH[j]);
                h[j] = fmaf(z[j], Hc - h[j], h[j]);   // h*(1-z) + z*Hc
            }
            if (layer < NL - 1) {
                float4* op = (float4*)(outbase + (long long)t * NB * HD);
                op[0] = make_float4(h[0], h[1], h[2], h[3]);
                op[1] = make_float4(h[4], h[5], h[6], h[7]);
            }
        }
        if (layer < NL - 1) {
            __threadfence();
            __syncthreads();
            if (tid == 0) {
                unsigned int* fp = prodflag + t * CS;
                asm volatile("st.global.release.gpu.b32 [%0], %1;"
                             :: "l"(fp), "r"(1u) : "memory");
            }
        }
    }

    if (active) {
        if (out_size >= NB + NL * NB * HD) {
            float4* hp = (float4*)(out + NB + ((long long)layer * NB + b) * HD);
            hp[0] = make_float4(h[0], h[1], h[2], h[3]);
            hp[1] = make_float4(h[4], h[5], h[6], h[7]);
        }
        if (layer == NL - 1) {
            float acc = by[0];
            #pragma unroll
            for (int j = 0; j < 8; j++) acc = fmaf(h[j], Why[j], acc);
            out[b] = acc;
        }
    }
}

extern "C" void kernel_launch(void* const* d_in, const int* in_sizes, int n_in,
                              void* d_out, int out_size) {
    const int*   x    = (const int*)d_in[0];
    const float* emb  = (const float*)d_in[1];
    const float* Wxz0 = (const float*)d_in[2];
    const float* Whz0 = (const float*)d_in[3];
    const float* bz0  = (const float*)d_in[4];
    const float* Wxr0 = (const float*)d_in[5];
    const float* Whr0 = (const float*)d_in[6];
    const float* br0  = (const float*)d_in[7];
    const float* WxH0 = (const float*)d_in[8];
    const float* WrH0 = (const float*)d_in[9];
    const float* bH0  = (const float*)d_in[10];
    const float* Wxz  = (const float*)d_in[11];
    const float* Whz  = (const float*)d_in[12];
    const float* bz   = (const float*)d_in[13];
    const float* Wxr  = (const float*)d_in[14];
    const float* Whr  = (const float*)d_in[15];
    const float* br   = (const float*)d_in[16];
    const float* WxH  = (const float*)d_in[17];
    const float* WrH  = (const float*)d_in[18];
    const float* bH   = (const float*)d_in[19];
    const float* Why  = (const float*)d_in[20];
    const float* by   = (const float*)d_in[21];
    float* out = (float*)d_out;

    clear_flags<<<(24 * NS * CS + 1023) / 1024, 1024>>>();
    precompute_xproj<<<(NB * NS + 255) / 256, 256>>>(x, emb, Wxz0, bz0, Wxr0, br0, WxH0, bH0);
    gru_pipeline<<<NL * CS, 256>>>(Whz0, Whr0, WrH0,
                                   Wxz, Whz, bz, Wxr, Whr, br, WxH, WrH, bH,
                                   Why, by, out, out_size);
}

// round 3
// speedup vs baseline: 1.2976x; 1.2976x over previous
#include <cuda_runtime.h>

#define NL 25
#define ED 64
#define HD 8
#define NB 1000
#define NS 512
#define CS 5          // CTAs (batch slices) per layer
#define BPC 200       // batches per CTA

typedef unsigned long long u64;

// Scratch (static __device__ arrays; allocation-free per harness rules)
__device__ float g_xproj[NS * NB * 24];                    // layer-0 x-projections (+bias)
__device__ float g_hbuf[(NL - 1) * NS * NB * HD];          // inter-layer h buffers
__device__ unsigned int g_flags[(NL - 1) * NS * NB];       // per-thread ready flags

// ---------- f32x2 packed-FMA helpers (FFMA2 only reachable via PTX) ----------
__device__ __forceinline__ u64 pk2(float v) {
    u64 d; asm("mov.b64 %0,{%1,%1};" : "=l"(d) : "f"(v)); return d;
}
__device__ __forceinline__ u64 pkab(float a, float b) {
    u64 d; asm("mov.b64 %0,{%1,%2};" : "=l"(d) : "f"(a), "f"(b)); return d;
}
__device__ __forceinline__ void upk(u64 v, float& a, float& b) {
    asm("mov.b64 {%0,%1},%2;" : "=f"(a), "=f"(b) : "l"(v));
}
__device__ __forceinline__ u64 f2fma(u64 a, u64 b, u64 c) {
    u64 d; asm("fma.rn.f32x2 %0,%1,%2,%3;" : "=l"(d) : "l"(a), "l"(b), "l"(c)); return d;
}
__device__ __forceinline__ u64 f2add(u64 a, u64 b) {
    u64 d; asm("add.rn.f32x2 %0,%1,%2;" : "=l"(d) : "l"(a), "l"(b)); return d;
}
// acc[0..3] (8 floats) += s2 * w_row[0..3]
__device__ __forceinline__ void fma8p(u64* acc, u64 s2, const u64* w) {
    acc[0] = f2fma(s2, w[0], acc[0]); acc[1] = f2fma(s2, w[1], acc[1]);
    acc[2] = f2fma(s2, w[2], acc[2]); acc[3] = f2fma(s2, w[3], acc[3]);
}

__device__ __forceinline__ float sigm(float x) {
    return __fdividef(1.0f, 1.0f + __expf(-x));
}
__device__ __forceinline__ float tanh_f(float x) {
    return 1.0f - __fdividef(2.0f, __expf(2.0f * x) + 1.0f);
}

// ---------- precompute: layer-0 x-projections + flag clear ----------
// xproj[t][b][0:8]=x@Wxz0+bz0, [8:16]=x@Wxr0+br0, [16:24]=x@WxH0+bH0
__global__ void __launch_bounds__(256) precompute_xproj(
    const int* __restrict__ x, const float* __restrict__ emb,
    const float* __restrict__ Wxz0, const float* __restrict__ bz0,
    const float* __restrict__ Wxr0, const float* __restrict__ br0,
    const float* __restrict__ WxH0, const float* __restrict__ bH0)
{
    __shared__ __align__(16) float sw[3][ED][8];
    __shared__ __align__(16) float sb[24];
    const int tid = threadIdx.x;
    for (int i = tid; i < ED * HD; i += blockDim.x) {
        ((float*)sw[0])[i] = Wxz0[i];
        ((float*)sw[1])[i] = Wxr0[i];
        ((float*)sw[2])[i] = WxH0[i];
    }
    if (tid < 8) { sb[tid] = bz0[tid]; sb[8 + tid] = br0[tid]; sb[16 + tid] = bH0[tid]; }
    __syncthreads();

    const int gid = blockIdx.x * blockDim.x + tid;   // exactly NB*NS = 512000 threads

    // clear flags: (NL-1)*NS*NB u32 = 12,288,000 = 3,072,000 uint4, coalesced
    {
        uint4 z4 = make_uint4(0u, 0u, 0u, 0u);
        uint4* f4 = (uint4*)g_flags;
        #pragma unroll
        for (int j = 0; j < 6; j++) f4[gid + j * (NB * NS)] = z4;
    }

    if (gid >= NB * NS) return;
    const int b = gid / NS, t = gid % NS;
    const int idx = x[gid];
    const float4* e4 = (const float4*)(emb + (long long)idx * ED);

    const u64 (*wz)[4] = (const u64(*)[4])sw[0];
    const u64 (*wr)[4] = (const u64(*)[4])sw[1];
    const u64 (*wH)[4] = (const u64(*)[4])sw[2];
    const u64* sb2 = (const u64*)sb;

    u64 acc[12];
    #pragma unroll
    for (int j = 0; j < 12; j++) acc[j] = sb2[j];

    #pragma unroll
    for (int k4 = 0; k4 < ED / 4; k4++) {
        float4 ev = e4[k4];
        float es[4] = {ev.x, ev.y, ev.z, ev.w};
        #pragma unroll
        for (int q = 0; q < 4; q++) {
            const int k = k4 * 4 + q;
            const u64 s2 = pk2(es[q]);
            fma8p(acc,     s2, wz[k]);
            fma8p(acc + 4, s2, wr[k]);
            fma8p(acc + 8, s2, wH[k]);
        }
    }
    float o[24];
    #pragma unroll
    for (int j = 0; j < 12; j++) upk(acc[j], o[2 * j], o[2 * j + 1]);
    float4* o4 = (float4*)(g_xproj + ((long long)t * NB + b) * 24);
    #pragma unroll
    for (int j = 0; j < 6; j++)
        o4[j] = make_float4(o[4 * j], o[4 * j + 1], o[4 * j + 2], o[4 * j + 3]);
}

// ---------- persistent layer-pipelined GRU ----------
// blockIdx = layer*CS + slice. No intra-loop barriers: per-thread release/acquire
// handshake (thread b of layer l consumes exactly thread b of layer l-1).
__global__ void __launch_bounds__(256, 1) gru_pipeline(
    const float* __restrict__ Whz0, const float* __restrict__ Whr0, const float* __restrict__ WrH0,
    const float* __restrict__ Wxz, const float* __restrict__ Whz, const float* __restrict__ bz,
    const float* __restrict__ Wxr, const float* __restrict__ Whr, const float* __restrict__ br,
    const float* __restrict__ WxH, const float* __restrict__ WrH, const float* __restrict__ bH,
    const float* __restrict__ Why, const float* __restrict__ by,
    float* __restrict__ out, int out_size)
{
    __shared__ __align__(16) float sw[6][HD][8];  // 0 Wxz | 1 Whz | 2 Wxr | 3 Whr | 4 WxH | 5 WrH
    __shared__ __align__(16) float sb[24];
    const int tid = threadIdx.x;
    const int layer = blockIdx.x / CS;
    const int c = blockIdx.x % CS;

    if (layer == 0) {
        // layer-0 slots: 0 = Whz0, 1 = Whr0, 2 = WrH0 (x-parts + biases live in g_xproj)
        for (int i = tid; i < HD * HD; i += blockDim.x) {
            ((float*)sw[0])[i] = Whz0[i];
            ((float*)sw[1])[i] = Whr0[i];
            ((float*)sw[2])[i] = WrH0[i];
        }
    } else {
        const int off = (layer - 1) * HD * HD;
        for (int i = tid; i < HD * HD; i += blockDim.x) {
            ((float*)sw[0])[i] = Wxz[off + i];
            ((float*)sw[1])[i] = Whz[off + i];
            ((float*)sw[2])[i] = Wxr[off + i];
            ((float*)sw[3])[i] = Whr[off + i];
            ((float*)sw[4])[i] = WxH[off + i];
            ((float*)sw[5])[i] = WrH[off + i];
        }
        if (tid < 8) {
            sb[tid]      = bz[(layer - 1) * 8 + tid];
            sb[8 + tid]  = br[(layer - 1) * 8 + tid];
            sb[16 + tid] = bH[(layer - 1) * 8 + tid];
        }
    }
    __syncthreads();
    if (tid >= BPC) return;

    const int b = c * BPC + tid;
    const u64 (*wxz2)[4] = (const u64(*)[4])sw[0];
    const u64 (*whz2)[4] = (const u64(*)[4])sw[1];
    const u64 (*wxr2)[4] = (const u64(*)[4])sw[2];
    const u64 (*whr2)[4] = (const u64(*)[4])sw[3];
    const u64 (*wxH2)[4] = (const u64(*)[4])sw[4];
    const u64 (*wrH2)[4] = (layer == 0) ? (const u64(*)[4])sw[2] : (const u64(*)[4])sw[5];
    // layer 0 h-gates sit in slots 0/1
    const u64 (*hz2)[4] = (layer == 0) ? (const u64(*)[4])sw[0] : whz2;
    const u64 (*hr2)[4] = (layer == 0) ? (const u64(*)[4])sw[1] : whr2;

    u64 bz2[4], br2[4], bH2[4];
    if (layer > 0) {
        const u64* sb2 = (const u64*)sb;
        #pragma unroll
        for (int j = 0; j < 4; j++) { bz2[j] = sb2[j]; br2[j] = sb2[4 + j]; bH2[j] = sb2[8 + j]; }
    }

    float h[8];
    #pragma unroll
    for (int j = 0; j < 8; j++) h[j] = 0.f;

    const unsigned int* consflag = (layer > 0)
        ? g_flags + ((long long)(layer - 1) * NS) * NB + b : 0;
    unsigned int* prodflag = (layer < NL - 1)
        ? g_flags + ((long long)layer * NS) * NB + b : 0;
    const float* inbase = (layer > 0)
        ? g_hbuf + (((long long)(layer - 1) * NS) * NB + b) * HD : 0;
    float* outbase = (layer < NL - 1)
        ? g_hbuf + (((long long)layer * NS) * NB + b) * HD : 0;
    const float* xpbase = g_xproj + (long long)b * 24;

    #pragma unroll 1
    for (int t = 0; t < NS; t++) {
        u64 az[4], ar[4], aH[4];
        if (layer == 0) {
            // issue x-projection loads early, overlap with h-part FMAs
            const float4* xp = (const float4*)(xpbase + (long long)t * NB * 24);
            float4 v0 = __ldcg(xp + 0), v1 = __ldcg(xp + 1), v2 = __ldcg(xp + 2);
            float4 v3 = __ldcg(xp + 3), v4 = __ldcg(xp + 4), v5 = __ldcg(xp + 5);
            #pragma unroll
            for (int j = 0; j < 4; j++) { az[j] = 0ull; ar[j] = 0ull; }
            #pragma unroll
            for (int k = 0; k < 8; k++) {
                const u64 h2 = pk2(h[k]);
                fma8p(az, h2, hz2[k]);
                fma8p(ar, h2, hr2[k]);
            }
            az[0] = f2add(az[0], pkab(v0.x, v0.y)); az[1] = f2add(az[1], pkab(v0.z, v0.w));
            az[2] = f2add(az[2], pkab(v1.x, v1.y)); az[3] = f2add(az[3], pkab(v1.z, v1.w));
            ar[0] = f2add(ar[0], pkab(v2.x, v2.y)); ar[1] = f2add(ar[1], pkab(v2.z, v2.w));
            ar[2] = f2add(ar[2], pkab(v3.x, v3.y)); ar[3] = f2add(ar[3], pkab(v3.z, v3.w));
            aH[0] = pkab(v4.x, v4.y); aH[1] = pkab(v4.z, v4.w);
            aH[2] = pkab(v5.x, v5.y); aH[3] = pkab(v5.z, v5.w);
        } else {
            // h-recurrent halves first (independent of incoming x) — hides the hop
            #pragma unroll
            for (int j = 0; j < 4; j++) { az[j] = bz2[j]; ar[j] = br2[j]; aH[j] = bH2[j]; }
            #pragma unroll
            for (int k = 0; k < 8; k++) {
                const u64 h2 = pk2(h[k]);
                fma8p(az, h2, hz2[k]);
                fma8p(ar, h2, hr2[k]);
            }
            // acquire-poll own flag
            {
                const unsigned int* fp = consflag + (long long)t * NB;
                unsigned int f;
                do {
                    asm volatile("ld.global.acquire.gpu.b32 %0, [%1];"
                                 : "=r"(f) : "l"(fp) : "memory");
                } while (f == 0u);
            }
            const float4* xi = (const float4*)(inbase + (long long)t * NB * HD);
            float4 x0 = __ldcg(xi), x1 = __ldcg(xi + 1);
            float xk[8] = {x0.x, x0.y, x0.z, x0.w, x1.x, x1.y, x1.z, x1.w};
            #pragma unroll
            for (int k = 0; k < 8; k++) {
                const u64 x2 = pk2(xk[k]);
                fma8p(az, x2, wxz2[k]);
                fma8p(ar, x2, wxr2[k]);
                fma8p(aH, x2, wxH2[k]);
            }
        }
        // gates
        float azf[8], arf[8], z[8], r[8];
        #pragma unroll
        for (int j = 0; j < 4; j++) { upk(az[j], azf[2 * j], azf[2 * j + 1]);
                                      upk(ar[j], arf[2 * j], arf[2 * j + 1]); }
        #pragma unroll
        for (int j = 0; j < 8; j++) { z[j] = sigm(azf[j]); r[j] = sigm(arf[j]); }
        #pragma unroll
        for (int k = 0; k < 8; k++) fma8p(aH, pk2(h[k] * r[k]), wrH2[k]);
        float aHf[8];
        #pragma unroll
        for (int j = 0; j < 4; j++) upk(aH[j], aHf[2 * j], aHf[2 * j + 1]);
        #pragma unroll
        for (int j = 0; j < 8; j++) {
            const float Hc = tanh_f(aHf[j]);
            h[j] = fmaf(z[j], Hc - h[j], h[j]);
        }
        if (layer < NL - 1) {
            float4* op = (float4*)(outbase + (long long)t * NB * HD);
            op[0] = make_float4(h[0], h[1], h[2], h[3]);
            op[1] = make_float4(h[4], h[5], h[6], h[7]);
            unsigned int* fp = prodflag + (long long)t * NB;
            asm volatile("st.global.release.gpu.b32 [%0], %1;"
                         :: "l"(fp), "r"(1u) : "memory");
        }
    }

    if (out_size >= NB + NL * NB * HD) {
        float4* hp = (float4*)(out + NB + ((long long)layer * NB + b) * HD);
        hp[0] = make_float4(h[0], h[1], h[2], h[3]);
        hp[1] = make_float4(h[4], h[5], h[6], h[7]);
    }
    if (layer == NL - 1) {
        float acc = by[0];
        #pragma unroll
        for (int j = 0; j < 8; j++) acc = fmaf(h[j], Why[j], acc);
        out[b] = acc;
    }
}

extern "C" void kernel_launch(void* const* d_in, const int* in_sizes, int n_in,
                              void* d_out, int out_size) {
    const int*   x    = (const int*)d_in[0];
    const float* emb  = (const float*)d_in[1];
    const float* Wxz0 = (const float*)d_in[2];
    const float* Whz0 = (const float*)d_in[3];
    const float* bz0  = (const float*)d_in[4];
    const float* Wxr0 = (const float*)d_in[5];
    const float* Whr0 = (const float*)d_in[6];
    const float* br0  = (const float*)d_in[7];
    const float* WxH0 = (const float*)d_in[8];
    const float* WrH0 = (const float*)d_in[9];
    const float* bH0  = (const float*)d_in[10];
    const float* Wxz  = (const float*)d_in[11];
    const float* Whz  = (const float*)d_in[12];
    const float* bz   = (const float*)d_in[13];
    const float* Wxr  = (const float*)d_in[14];
    const float* Whr  = (const float*)d_in[15];
    const float* br   = (const float*)d_in[16];
    const float* WxH  = (const float*)d_in[17];
    const float* WrH  = (const float*)d_in[18];
    const float* bH   = (const float*)d_in[19];
    const float* Why  = (const float*)d_in[20];
    const float* by   = (const float*)d_in[21];
    float* out = (float*)d_out;

    precompute_xproj<<<(NB * NS + 255) / 256, 256>>>(x, emb, Wxz0, bz0, Wxr0, br0, WxH0, bH0);
    gru_pipeline<<<NL * CS, 256>>>(Whz0, Whr0, WrH0,
                                   Wxz, Whz, bz, Wxr, Whr, br, WxH, WrH, bH,
                                   Why, by, out, out_size);
}